// round 14
// baseline (speedup 1.0000x reference)
#include <cuda_runtime.h>
#include <math.h>
#include <stdint.h>

// Problem constants
#define B_   8
#define P_   16384
#define M_   16
#define CI_  16
#define CO_  32
#define W_   17
#define OSTRIDE 288       // floats per output row in Wf (17 w-slots + residual col)
#define WWM  24           // per-m stride in ww_s (2 wp-halves of 12)
#define WARP_SM 400       // per-warp smem floats: ww 16*24=384 + nb 16

typedef unsigned long long ull;

// packed f32x2 (SASS FFMA2) — only reachable via PTX
#define FMA_F32X2(d, a, b, c) \
    asm("fma.rn.f32x2 %0, %1, %2, %3;" : "=l"(d) : "l"(a), "l"(b), "l"(c))
#define MUL_F32X2(d, a, b) \
    asm("mul.rn.f32x2 %0, %1, %2;" : "=l"(d) : "l"(a), "l"(b))
#define PACK_REPL_F32X2(out, s) \
    asm("mov.b64 %0, {%1, %1};" : "=l"(out) : "r"(s))
#define UNPACK_F32X2(lo, hi, in) \
    asm("mov.b64 {%0, %1}, %2;" : "=r"(lo), "=r"(hi) : "l"(in))

// smem (floats): Wf [32][288] = 9216 ; per-warp (4): ww[16][24] + nb[16] = 400
// total = 9216 + 1600 = 10816 floats = 43264 bytes

__global__ void __launch_bounds__(128, 4)
fused_conv_kernel(const float* __restrict__ in_pc,
                  const float* __restrict__ weights,
                  const float* __restrict__ bias,
                  const float* __restrict__ w_weights,
                  const float* __restrict__ weight_res,
                  const int*   __restrict__ neighbor_id,
                  float*       __restrict__ out)
{
    constexpr float SQ_CONV = 0.70710678118654752440f;
    constexpr float SQ_RES  = 0.70710678118654752440f;

    extern __shared__ float sm[];
    float* Wf = sm;                                   // [32][288]

    const int tid  = threadIdx.x;
    const int warp = tid >> 5;
    const int lane = tid & 31;

    float* ww_s = sm + 32 * OSTRIDE + warp * WARP_SM; // [16][24]
    int*   nb_s = (int*)(ww_s + 384);                 // [16]

    // ---- stage weights: Wf[o][w*16+i]; col 272..287 = weight_res[o][:] ----
    for (int idx = tid; idx < W_ * 512; idx += 128) {
        int w   = idx >> 9;
        int rem = idx & 511;
        int o   = rem >> 4;
        int i   = rem & 15;
        Wf[o * OSTRIDE + w * 16 + i] = weights[idx];
    }
    for (int idx = tid; idx < 512; idx += 128) {
        int o = idx >> 4, i = idx & 15;
        Wf[o * OSTRIDE + 272 + i] = weight_res[idx];
    }

    const int p = blockIdx.x * 4 + warp;

    // ---- per-warp staging: neighbor ids, masked ww (parity-split layout) ----
    if (lane < 16) {
        nb_s[lane] = neighbor_id[p * M_ + lane];
        ww_s[lane * WWM + 12 + 8] = 0.0f;     // wp1 slot8 = 0 (keeps gacc2[8]=0)
    }
    __syncwarp();
    for (int idx = lane; idx < 272; idx += 32) {
        int m = idx / 17;
        int w = idx - m * 17;
        float v = w_weights[(size_t)p * 272 + idx];
        // slot: wp = w&1 ; s = w>>1  (w=16 -> wp0 s8)
        ww_s[m * WWM + (w & 1) * 12 + (w >> 1)] = (nb_s[m] == P_) ? 0.0f : v;
    }
    __syncthreads();

    // lane bits: bg = bit4 ; wp = bit3 ; ih (channel pair) = bits 0-2
    // XOR-permuted slot ownership: oL = (lane>>2)&3 (= wp*2 + h2), jL = lane&3.
    const int bg = (lane >> 4) & 1;
    const int wp = (lane >> 3) & 1;
    const int ih = lane & 7;
    const int oL = (lane >> 2) & 3;
    const int jL = lane & 3;
    const int b_fin = bg + 2 * jL;

    // physical batch slot sj holds batch b = bg + 2*(sj ^ jL)
    const float* xb[4];
    #pragma unroll
    for (int sj = 0; sj < 4; sj++)
        xb[sj] = in_pc + (size_t)(bg + 2 * (sj ^ jL)) * P_ * CI_ + 2 * ih;

    // residual input: this lane's channel-QUARTER (q = oL) of its own (b_fin, p)
    ull xq0, xq1;
    {
        const ull* xqp = (const ull*)(in_pc + ((size_t)b_fin * P_ + p) * CI_ + oL * 4);
        xq0 = xqp[0];
        xq1 = xqp[1];
    }

    // gacc2[s][sj]: packed ch-pair accumulators. s=0..7: w=2s+wp ;
    // s=8: wp0 -> w=16 conv ; wp1 -> zero (ww slot8 = 0)
    ull gacc2[9][4];
    #pragma unroll
    for (int s = 0; s < 9; s++) {
        gacc2[s][0] = 0ull; gacc2[s][1] = 0ull;
        gacc2[s][2] = 0ull; gacc2[s][3] = 0ull;
    }

    // ---- stage A ----
    const float* wwp = ww_s + wp * 12;
    #pragma unroll 4
    for (int m = 0; m < M_; m++) {
        int nb  = nb_s[m];
        int nbc = (nb == P_) ? 0 : nb;          // ww zeroed for pad
        size_t xo = (size_t)nbc * CI_;
        ull x0 = *(const ull*)(xb[0] + xo);
        ull x1 = *(const ull*)(xb[1] + xo);
        ull x2 = *(const ull*)(xb[2] + xo);
        ull x3 = *(const ull*)(xb[3] + xo);
        const float* wm = wwp + m * WWM;
        float4 fA = *(const float4*)(wm);
        float4 fB = *(const float4*)(wm + 4);
        float  f8 = wm[8];
        float fs[9] = {fA.x, fA.y, fA.z, fA.w, fB.x, fB.y, fB.z, fB.w, f8};
        #pragma unroll
        for (int s = 0; s < 9; s++) {
            ull f2;
            uint32_t fb = __float_as_uint(fs[s]);
            PACK_REPL_F32X2(f2, fb);
            FMA_F32X2(gacc2[s][0], f2, x0, gacc2[s][0]);
            FMA_F32X2(gacc2[s][1], f2, x1, gacc2[s][1]);
            FMA_F32X2(gacc2[s][2], f2, x2, gacc2[s][2]);
            FMA_F32X2(gacc2[s][3], f2, x3, gacc2[s][3]);
        }
    }

    // ---- stage B: XOR-permuted slots; each Wf LDS.64 feeds 4 FFMA2 ----
    const float* wfb = Wf + wp * 16 + 2 * ih;
    const float* biasp = bias + (size_t)p * CO_;
    float* outb = out + ((size_t)b_fin * P_ + p) * CO_;

    #pragma unroll 2
    for (int og = 0; og < 8; og++) {
        float av[4][4];
        float pr[4];

        #pragma unroll
        for (int so = 0; so < 4; so++) {
            const int row = og * 4 + (so ^ oL);
            const float* wfoo = wfb + (size_t)row * OSTRIDE;

            ull acc2[4] = {0ull, 0ull, 0ull, 0ull};
            #pragma unroll
            for (int s = 0; s < 8; s++) {
                ull wv = *(const ull*)(wfoo + s * 32);
                FMA_F32X2(acc2[0], wv, gacc2[s][0], acc2[0]);
                FMA_F32X2(acc2[1], wv, gacc2[s][1], acc2[1]);
                FMA_F32X2(acc2[2], wv, gacc2[s][2], acc2[2]);
                FMA_F32X2(acc2[3], wv, gacc2[s][3], acc2[3]);
            }
            // slot 8: wp0 -> conv w=16 ; wp1 -> wres col * gacc2[8](=0) = 0
            ull wv8 = *(const ull*)(wfoo + 256);
            FMA_F32X2(acc2[0], wv8, gacc2[8][0], acc2[0]);
            FMA_F32X2(acc2[1], wv8, gacc2[8][1], acc2[1]);
            FMA_F32X2(acc2[2], wv8, gacc2[8][2], acc2[2]);
            FMA_F32X2(acc2[3], wv8, gacc2[8][3], acc2[3]);

            #pragma unroll
            for (int sj = 0; sj < 4; sj++) {
                uint32_t lo, hi;
                UNPACK_F32X2(lo, hi, acc2[sj]);
                av[so][sj] = __uint_as_float(lo) + __uint_as_float(hi);
            }

            // residual partial: quarter q = oL of wres row (un-swizzled base!)
            {
                const float* wrow = Wf + (size_t)row * OSTRIDE + 272 + oL * 4;
                ull w2a = *(const ull*)(wrow);
                ull w2b = *(const ull*)(wrow + 2);
                ull t2;
                MUL_F32X2(t2, w2a, xq0);
                FMA_F32X2(t2, w2b, xq1, t2);
                uint32_t lo, hi;
                UNPACK_F32X2(lo, hi, t2);
                pr[so] = __uint_as_float(lo) + __uint_as_float(hi);
            }
        }

        // ---- select-free reduce-scatter (recursive halving, XOR slots) ----
        #pragma unroll
        for (int so = 0; so < 2; so++) {
            #pragma unroll
            for (int sj = 0; sj < 4; sj++)
                av[so][sj] += __shfl_xor_sync(0xffffffffu, av[so + 2][sj], 8);
        }
        // residual ladder: quarters live on (wp,h2) lanes -> xor8 then xor4 only
        pr[0] += __shfl_xor_sync(0xffffffffu, pr[2], 8);
        pr[1] += __shfl_xor_sync(0xffffffffu, pr[3], 8);
        pr[0] += __shfl_xor_sync(0xffffffffu, pr[1], 4);

        #pragma unroll
        for (int sj = 0; sj < 4; sj++)
            av[0][sj] += __shfl_xor_sync(0xffffffffu, av[1][sj], 4);
        #pragma unroll
        for (int sj = 0; sj < 2; sj++)
            av[0][sj] += __shfl_xor_sync(0xffffffffu, av[0][sj + 2], 2);
        av[0][0] += __shfl_xor_sync(0xffffffffu, av[0][1], 1);

        // ---- epilogue: lane owns (o = og*4 + oL, b = b_fin) ----
        const int o = og * 4 + oL;
        float c = av[0][0] + biasp[o];
        float e = (c > 0.0f) ? c : expm1f(c);
        outb[o] = e * SQ_CONV + pr[0] * SQ_RES;
    }
}

extern "C" void kernel_launch(void* const* d_in, const int* in_sizes, int n_in,
                              void* d_out, int out_size)
{
    const float* in_pc       = nullptr;
    const float* weights     = nullptr;
    const float* bias        = nullptr;
    const float* w_weights   = nullptr;
    const float* weight_res  = nullptr;
    const int*   neighbor_id = nullptr;

    for (int i = 0; i < n_in; i++) {
        switch (in_sizes[i]) {
            case 2097152: in_pc       = (const float*)d_in[i]; break; // (8,16384,16)
            case 8704:    weights     = (const float*)d_in[i]; break; // (17,512)
            case 524288:  bias        = (const float*)d_in[i]; break; // (16384,32)
            case 4456448: w_weights   = (const float*)d_in[i]; break; // (16384,16,17)
            case 512:     weight_res  = (const float*)d_in[i]; break; // (32,16)
            case 262144:  neighbor_id = (const int*)d_in[i];   break; // (16384,16)
            default: break;
        }
    }

    const int smem_bytes = (32 * OSTRIDE + 4 * WARP_SM) * 4; // 43264
    cudaFuncSetAttribute(fused_conv_kernel,
                         cudaFuncAttributeMaxDynamicSharedMemorySize, smem_bytes);

    fused_conv_kernel<<<P_ / 4, 128, smem_bytes>>>(
        in_pc, weights, bias, w_weights, weight_res, neighbor_id, (float*)d_out);
}

// round 16
// speedup vs baseline: 1.0306x; 1.0306x over previous
#include <cuda_runtime.h>
#include <cuda_bf16.h>
#include <math.h>
#include <stdint.h>

#define B_   8
#define P_   16384
#define M_   16
#define CI_  16
#define CO_  32
#define W_   17
#define WWM  24
#define PTS  16
#define NTHR 512

typedef unsigned long long ull;

#define FMA_F32X2(d, a, b, c) \
    asm("fma.rn.f32x2 %0, %1, %2, %3;" : "=l"(d) : "l"(a), "l"(b), "l"(c))
#define MUL_F32X2(d, a, b) \
    asm("mul.rn.f32x2 %0, %1, %2;" : "=l"(d) : "l"(a), "l"(b))
#define PACK_REPL_F32X2(out, s) \
    asm("mov.b64 %0, {%1, %1};" : "=l"(out) : "r"(s))
#define UNPACK_F32X2(lo, hi, in) \
    asm("mov.b64 {%0, %1}, %2;" : "=r"(lo), "=r"(hi) : "l"(in))

// ---- smem byte layout ----
// G rows: 128, row stride 624B (272 bf16 data + pad; 624%128=112 -> ldmatrix
// conflict-free; dead s=8/wp=1 writes land at k in [272,288) < 312, never read)
#define GSTRIDE   624u
#define SM_G_HI   0u
#define SM_G_LO   79872u      // 128*624 ; ww/nb overlay (25600B) lives here pre-split
#define SM_W_HI   159744u     // Wf rows: 32 x 624B
#define SM_W_LO   179712u
#define SM_RES    199680u     // float res[128][32], pre-scaled by SQ_RES
#define SM_WRES   216064u     // float wres[32][16]
#define SM_TOTAL  218112u

__device__ __forceinline__ uint32_t smem_u32(const void* p) {
    uint32_t a;
    asm("{ .reg .u64 t; cvta.to.shared.u64 t, %1; cvt.u32.u64 %0, t; }" : "=r"(a) : "l"(p));
    return a;
}
#define LDMATRIX_X4(r0, r1, r2, r3, addr) \
    asm volatile("ldmatrix.sync.aligned.m8n8.x4.shared.b16 {%0,%1,%2,%3}, [%4];" \
                 : "=r"(r0), "=r"(r1), "=r"(r2), "=r"(r3) : "r"(addr))
#define MMA_BF16(c, a, b0, b1) \
    asm volatile("mma.sync.aligned.m16n8k16.row.col.f32.bf16.bf16.f32 " \
                 "{%0,%1,%2,%3}, {%4,%5,%6,%7}, {%8,%9}, {%0,%1,%2,%3};" \
                 : "+f"((c)[0]), "+f"((c)[1]), "+f"((c)[2]), "+f"((c)[3]) \
                 : "r"((a)[0]), "r"((a)[1]), "r"((a)[2]), "r"((a)[3]), \
                   "r"(b0), "r"(b1))

__global__ void __launch_bounds__(NTHR, 1)
fused_conv_mma_kernel(const float* __restrict__ in_pc,
                      const float* __restrict__ weights,
                      const float* __restrict__ bias,
                      const float* __restrict__ w_weights,
                      const float* __restrict__ weight_res,
                      const int*   __restrict__ neighbor_id,
                      float*       __restrict__ out)
{
    constexpr float SQ_CONV = 0.70710678118654752440f;
    constexpr float SQ_RES  = 0.70710678118654752440f;

    extern __shared__ char smc[];
    float* sm_f = (float*)smc;
    const uint32_t smb = smem_u32(smc);

    const int tid  = threadIdx.x;
    const int warp = tid >> 5;
    const int lane = tid & 31;
    const int pbase = blockIdx.x * PTS;
    const int p = pbase + warp;          // stage-A point for this warp

    float* wres_s = sm_f + (SM_WRES >> 2);
    float* res_s  = sm_f + (SM_RES  >> 2);
    float* ww_s   = (float*)(smc + SM_G_LO) + warp * 400;   // overlay, dead after stage A
    int*   nb_s   = (int*)(ww_s + 384);

    // ---- Wf tiles: weights[w][o*16+i] -> bf16 hi/lo rows [o][k=w*16+i] ----
    for (int idx = tid; idx < W_ * 512; idx += NTHR) {
        int w = idx >> 9;
        int rem = idx & 511;
        int o = rem >> 4, i = rem & 15;
        float v = weights[idx];
        __nv_bfloat16 h = __float2bfloat16(v);
        __nv_bfloat16 l = __float2bfloat16(v - __bfloat162float(h));
        uint32_t off = (uint32_t)o * GSTRIDE + (uint32_t)(w * 16 + i) * 2u;
        *(__nv_bfloat16*)(smc + SM_W_HI + off) = h;
        *(__nv_bfloat16*)(smc + SM_W_LO + off) = l;
    }
    for (int idx = tid; idx < 512; idx += NTHR) wres_s[idx] = weight_res[idx];

    // ---- per-warp staging (R13 layout) ----
    if (lane < 16) {
        nb_s[lane] = neighbor_id[p * M_ + lane];
        ww_s[lane * WWM + 12 + 8] = 0.0f;
    }
    __syncwarp();
    for (int idx = lane; idx < 272; idx += 32) {
        int m = idx / 17;
        int w = idx - m * 17;
        float v = w_weights[(size_t)p * 272 + idx];
        ww_s[m * WWM + (w & 1) * 12 + (w >> 1)] = (nb_s[m] == P_) ? 0.0f : v;
    }
    __syncthreads();

    const int bg = (lane >> 4) & 1;
    const int wp = (lane >> 3) & 1;
    const int ih = lane & 7;
    const int oL = (lane >> 2) & 3;
    const int jL = lane & 3;
    const int b_fin = bg + 2 * jL;

    const float* xb[4];
    #pragma unroll
    for (int sj = 0; sj < 4; sj++)
        xb[sj] = in_pc + (size_t)(bg + 2 * (sj ^ jL)) * P_ * CI_ + 2 * ih;

    ull gacc2[9][4];
    #pragma unroll
    for (int s = 0; s < 9; s++) {
        gacc2[s][0] = 0ull; gacc2[s][1] = 0ull;
        gacc2[s][2] = 0ull; gacc2[s][3] = 0ull;
    }

    // ---- stage A (R13 verbatim) ----
    const float* wwp = ww_s + wp * 12;
    #pragma unroll 4
    for (int m = 0; m < M_; m++) {
        int nb  = nb_s[m];
        int nbc = (nb == P_) ? 0 : nb;
        size_t xo = (size_t)nbc * CI_;
        ull x0 = *(const ull*)(xb[0] + xo);
        ull x1 = *(const ull*)(xb[1] + xo);
        ull x2 = *(const ull*)(xb[2] + xo);
        ull x3 = *(const ull*)(xb[3] + xo);
        const float* wm = wwp + m * WWM;
        float4 fA = *(const float4*)(wm);
        float4 fB = *(const float4*)(wm + 4);
        float  f8 = wm[8];
        float fs[9] = {fA.x, fA.y, fA.z, fA.w, fB.x, fB.y, fB.z, fB.w, f8};
        #pragma unroll
        for (int s = 0; s < 9; s++) {
            ull f2;
            uint32_t fb = __float_as_uint(fs[s]);
            PACK_REPL_F32X2(f2, fb);
            FMA_F32X2(gacc2[s][0], f2, x0, gacc2[s][0]);
            FMA_F32X2(gacc2[s][1], f2, x1, gacc2[s][1]);
            FMA_F32X2(gacc2[s][2], f2, x2, gacc2[s][2]);
            FMA_F32X2(gacc2[s][3], f2, x3, gacc2[s][3]);
        }
    }

    // ---- residual (R13 quarter-ladder) -> res_s, pre-scaled by SQ_RES ----
    {
        const ull* xqp = (const ull*)(in_pc + ((size_t)b_fin * P_ + p) * CI_ + oL * 4);
        ull xq0 = xqp[0], xq1 = xqp[1];
        #pragma unroll
        for (int og = 0; og < 8; og++) {
            float pr[4];
            #pragma unroll
            for (int so = 0; so < 4; so++) {
                int row = og * 4 + (so ^ oL);
                const ull* wr = (const ull*)(wres_s + row * 16 + oL * 4);
                ull t2;
                MUL_F32X2(t2, wr[0], xq0);
                FMA_F32X2(t2, wr[1], xq1, t2);
                uint32_t lo, hi;
                UNPACK_F32X2(lo, hi, t2);
                pr[so] = __uint_as_float(lo) + __uint_as_float(hi);
            }
            pr[0] += __shfl_xor_sync(0xffffffffu, pr[2], 8);
            pr[1] += __shfl_xor_sync(0xffffffffu, pr[3], 8);
            pr[0] += __shfl_xor_sync(0xffffffffu, pr[1], 4);
            res_s[(warp * 8 + b_fin) * 32 + og * 4 + oL] = pr[0] * SQ_RES;
        }
    }
    __syncthreads();   // ww dead everywhere -> G_LO reusable

    // ---- split gacc2 -> bf16 hi/lo rows of G (row = warp*8 + b) ----
    #pragma unroll
    for (int s = 0; s < 9; s++) {
        const int kbase = (2 * s + wp) * 16 + 2 * ih;   // (s=8,wp=1): k>=272, pad only
        #pragma unroll
        for (int sj = 0; sj < 4; sj++) {
            const int row = warp * 8 + bg + 2 * (sj ^ jL);
            uint32_t u0, u1;
            UNPACK_F32X2(u0, u1, gacc2[s][sj]);
            float f0 = __uint_as_float(u0), f1 = __uint_as_float(u1);
            __nv_bfloat16 h0 = __float2bfloat16(f0), h1 = __float2bfloat16(f1);
            __nv_bfloat16 l0 = __float2bfloat16(f0 - __bfloat162float(h0));
            __nv_bfloat16 l1 = __float2bfloat16(f1 - __bfloat162float(h1));
            uint32_t hp = ((uint32_t)__bfloat16_as_ushort(h1) << 16) | __bfloat16_as_ushort(h0);
            uint32_t lp = ((uint32_t)__bfloat16_as_ushort(l1) << 16) | __bfloat16_as_ushort(l0);
            uint32_t off = (uint32_t)row * GSTRIDE + (uint32_t)kbase * 2u;
            *(uint32_t*)(smc + SM_G_HI + off) = hp;
            *(uint32_t*)(smc + SM_G_LO + off) = lp;
        }
    }
    __syncthreads();

    // ---- stage B: warp computes D tile [16 rows x 16 cols] via mma.sync ----
    // warp -> slice = warp>>1 (rows slice*16..), nhalf = (warp&1)*16
    {
        const int slice = warp >> 1;
        const int nhalf = (warp & 1) * 16;
        const int lm = lane >> 3;      // ldmatrix matrix id
        const int lr = lane & 7;

        // A addr: m0/m1 = row blocks, m2/m3 = +8 k-cols
        const uint32_t a_row = (uint32_t)(slice * 16 + lr + 8 * (lm & 1));
        const uint32_t a_kof = (uint32_t)(8 * (lm >> 1)) * 2u;
        // B addr: m0/m1 = k blocks of n-rows nhalf..+8, m2/m3 = n-rows +8
        const uint32_t b_row = (uint32_t)(nhalf + 8 * (lm >> 1) + lr);
        const uint32_t b_kof = (uint32_t)(8 * (lm & 1)) * 2u;

        const uint32_t ah_base = smb + SM_G_HI + a_row * GSTRIDE + a_kof;
        const uint32_t al_base = smb + SM_G_LO + a_row * GSTRIDE + a_kof;
        const uint32_t bh_base = smb + SM_W_HI + b_row * GSTRIDE + b_kof;
        const uint32_t bl_base = smb + SM_W_LO + b_row * GSTRIDE + b_kof;

        float c0[4] = {0.f, 0.f, 0.f, 0.f};   // n-tile 0 (cols nhalf..+8)
        float c1[4] = {0.f, 0.f, 0.f, 0.f};   // n-tile 1 (cols nhalf+8..+16)

        #pragma unroll 1
        for (int ks = 0; ks < 17; ks++) {
            const uint32_t ko = (uint32_t)(ks * 32);   // 16 bf16 = 32 B per kstep
            uint32_t ah[4], al[4], bh[4], bl[4];
            LDMATRIX_X4(ah[0], ah[1], ah[2], ah[3], ah_base + ko);
            LDMATRIX_X4(al[0], al[1], al[2], al[3], al_base + ko);
            LDMATRIX_X4(bh[0], bh[1], bh[2], bh[3], bh_base + ko);
            LDMATRIX_X4(bl[0], bl[1], bl[2], bl[3], bl_base + ko);
            MMA_BF16(c0, ah, bh[0], bh[1]);
            MMA_BF16(c1, ah, bh[2], bh[3]);
            MMA_BF16(c0, ah, bl[0], bl[1]);
            MMA_BF16(c1, ah, bl[2], bl[3]);
            MMA_BF16(c0, al, bh[0], bh[1]);
            MMA_BF16(c1, al, bh[2], bh[3]);
        }

        // ---- epilogue: c-frag lane l -> rows slice*16 + l/4 (+8), cols 2*(l%4) ----
        const int lr4 = lane >> 2;
        const int lc2 = (lane & 3) * 2;
        #pragma unroll
        for (int tile = 0; tile < 2; tile++) {
            const float* cc = tile ? c1 : c0;
            const int ncol = nhalf + tile * 8 + lc2;
            #pragma unroll
            for (int half = 0; half < 2; half++) {
                const int row = slice * 16 + lr4 + 8 * half;
                const int pt = row >> 3, b = row & 7;
                const float2 bz = *(const float2*)(bias + ((size_t)(pbase + pt)) * CO_ + ncol);
                const float2 rz = *(const float2*)(res_s + (size_t)row * 32 + ncol);
                float v0 = cc[half * 2 + 0] + bz.x;
                float v1 = cc[half * 2 + 1] + bz.y;
                float e0 = (v0 > 0.0f) ? v0 : expm1f(v0);
                float e1 = (v1 > 0.0f) ? v1 : expm1f(v1);
                float2 o2 = make_float2(e0 * SQ_CONV + rz.x, e1 * SQ_CONV + rz.y);
                *(float2*)(out + ((size_t)b * P_ + (pbase + pt)) * CO_ + ncol) = o2;
            }
        }
    }
}

extern "C" void kernel_launch(void* const* d_in, const int* in_sizes, int n_in,
                              void* d_out, int out_size)
{
    const float* in_pc       = nullptr;
    const float* weights     = nullptr;
    const float* bias        = nullptr;
    const float* w_weights   = nullptr;
    const float* weight_res  = nullptr;
    const int*   neighbor_id = nullptr;

    for (int i = 0; i < n_in; i++) {
        switch (in_sizes[i]) {
            case 2097152: in_pc       = (const float*)d_in[i]; break;
            case 8704:    weights     = (const float*)d_in[i]; break;
            case 524288:  bias        = (const float*)d_in[i]; break;
            case 4456448: w_weights   = (const float*)d_in[i]; break;
            case 512:     weight_res  = (const float*)d_in[i]; break;
            case 262144:  neighbor_id = (const int*)d_in[i];   break;
            default: break;
        }
    }

    cudaFuncSetAttribute(fused_conv_mma_kernel,
                         cudaFuncAttributeMaxDynamicSharedMemorySize, SM_TOTAL);

    fused_conv_mma_kernel<<<P_ / PTS, NTHR, SM_TOTAL>>>(
        in_pc, weights, bias, w_weights, weight_res, neighbor_id, (float*)d_out);
}

// round 17
// speedup vs baseline: 1.1277x; 1.0942x over previous
#include <cuda_runtime.h>
#include <cuda_bf16.h>
#include <math.h>
#include <stdint.h>

#define B_   8
#define P_   16384
#define M_   16
#define CI_  16
#define CO_  32
#define W_   17
#define WWM  24
#define PTS  8
#define NTHR 256

typedef unsigned long long ull;

#define FMA_F32X2(d, a, b, c) \
    asm("fma.rn.f32x2 %0, %1, %2, %3;" : "=l"(d) : "l"(a), "l"(b), "l"(c))
#define MUL_F32X2(d, a, b) \
    asm("mul.rn.f32x2 %0, %1, %2;" : "=l"(d) : "l"(a), "l"(b))
#define PACK_REPL_F32X2(out, s) \
    asm("mov.b64 %0, {%1, %1};" : "=l"(out) : "r"(s))
#define UNPACK_F32X2(lo, hi, in) \
    asm("mov.b64 {%0, %1}, %2;" : "=r"(lo), "=r"(hi) : "l"(in))

// ---- smem byte layout (115712 B -> 2 CTAs/SM) ----
// GSTRIDE 560: 272 bf16 data (544B) + 16B pad; 560%128=48 -> 8 consecutive
// rows hit distinct 16B groups {0,3,6,1,4,7,2,5}: ldmatrix conflict-free.
#define GSTRIDE   560u
#define SM_G_HI   0u          // 64 x 560 = 35840
#define SM_G_LO   35840u      // 35840 ; ww overlay (8w x 1600B = 12800) + wres
#define SM_WRES   48640u      // 2048 B, inside G_LO region (dead before split)
#define SM_W_HI   71680u      // 32 x 560 = 17920
#define SM_W_LO   89600u      // 17920
#define SM_RES    107520u     // float res[64][32] = 8192
#define SM_TOTAL  115712u

__device__ __forceinline__ uint32_t smem_u32(const void* p) {
    uint32_t a;
    asm("{ .reg .u64 t; cvta.to.shared.u64 t, %1; cvt.u32.u64 %0, t; }" : "=r"(a) : "l"(p));
    return a;
}
#define LDMATRIX_X4(r0, r1, r2, r3, addr) \
    asm volatile("ldmatrix.sync.aligned.m8n8.x4.shared.b16 {%0,%1,%2,%3}, [%4];" \
                 : "=r"(r0), "=r"(r1), "=r"(r2), "=r"(r3) : "r"(addr))
#define MMA_BF16(c, a, b0, b1) \
    asm volatile("mma.sync.aligned.m16n8k16.row.col.f32.bf16.bf16.f32 " \
                 "{%0,%1,%2,%3}, {%4,%5,%6,%7}, {%8,%9}, {%0,%1,%2,%3};" \
                 : "+f"((c)[0]), "+f"((c)[1]), "+f"((c)[2]), "+f"((c)[3]) \
                 : "r"((a)[0]), "r"((a)[1]), "r"((a)[2]), "r"((a)[3]), \
                   "r"(b0), "r"(b1))

__global__ void __launch_bounds__(NTHR, 2)
fused_conv_mma_kernel(const float* __restrict__ in_pc,
                      const float* __restrict__ weights,
                      const float* __restrict__ bias,
                      const float* __restrict__ w_weights,
                      const float* __restrict__ weight_res,
                      const int*   __restrict__ neighbor_id,
                      float*       __restrict__ out)
{
    constexpr float SQ_CONV = 0.70710678118654752440f;
    constexpr float SQ_RES  = 0.70710678118654752440f;

    extern __shared__ char smc[];
    float* sm_f = (float*)smc;
    const uint32_t smb = smem_u32(smc);

    const int tid  = threadIdx.x;
    const int warp = tid >> 5;
    const int lane = tid & 31;
    const int pbase = blockIdx.x * PTS;
    const int p = pbase + warp;          // stage-A point for this warp

    float* wres_s = sm_f + (SM_WRES >> 2);
    float* res_s  = sm_f + (SM_RES  >> 2);
    float* ww_s   = (float*)(smc + SM_G_LO) + warp * 400;   // overlay, dead after stage A
    int*   nb_s   = (int*)(ww_s + 384);

    // ---- Wf tiles: weights[w][o*16+i] -> bf16 hi/lo rows [o][k=w*16+i] ----
    for (int idx = tid; idx < W_ * 512; idx += NTHR) {
        int w = idx >> 9;
        int rem = idx & 511;
        int o = rem >> 4, i = rem & 15;
        float v = weights[idx];
        __nv_bfloat16 h = __float2bfloat16(v);
        __nv_bfloat16 l = __float2bfloat16(v - __bfloat162float(h));
        uint32_t off = (uint32_t)o * GSTRIDE + (uint32_t)(w * 16 + i) * 2u;
        *(__nv_bfloat16*)(smc + SM_W_HI + off) = h;
        *(__nv_bfloat16*)(smc + SM_W_LO + off) = l;
    }
    for (int idx = tid; idx < 512; idx += NTHR) wres_s[idx] = weight_res[idx];

    // ---- per-warp staging (R13 layout) ----
    if (lane < 16) {
        nb_s[lane] = neighbor_id[p * M_ + lane];
        ww_s[lane * WWM + 12 + 8] = 0.0f;
    }
    __syncwarp();
    for (int idx = lane; idx < 272; idx += 32) {
        int m = idx / 17;
        int w = idx - m * 17;
        float v = w_weights[(size_t)p * 272 + idx];
        ww_s[m * WWM + (w & 1) * 12 + (w >> 1)] = (nb_s[m] == P_) ? 0.0f : v;
    }
    __syncthreads();

    const int bg = (lane >> 4) & 1;
    const int wp = (lane >> 3) & 1;
    const int ih = lane & 7;
    const int oL = (lane >> 2) & 3;
    const int jL = lane & 3;
    const int b_fin = bg + 2 * jL;

    const float* xb[4];
    #pragma unroll
    for (int sj = 0; sj < 4; sj++)
        xb[sj] = in_pc + (size_t)(bg + 2 * (sj ^ jL)) * P_ * CI_ + 2 * ih;

    ull gacc2[9][4];
    #pragma unroll
    for (int s = 0; s < 9; s++) {
        gacc2[s][0] = 0ull; gacc2[s][1] = 0ull;
        gacc2[s][2] = 0ull; gacc2[s][3] = 0ull;
    }

    // ---- stage A (R13 verbatim) ----
    const float* wwp = ww_s + wp * 12;
    #pragma unroll 4
    for (int m = 0; m < M_; m++) {
        int nb  = nb_s[m];
        int nbc = (nb == P_) ? 0 : nb;
        size_t xo = (size_t)nbc * CI_;
        ull x0 = *(const ull*)(xb[0] + xo);
        ull x1 = *(const ull*)(xb[1] + xo);
        ull x2 = *(const ull*)(xb[2] + xo);
        ull x3 = *(const ull*)(xb[3] + xo);
        const float* wm = wwp + m * WWM;
        float4 fA = *(const float4*)(wm);
        float4 fB = *(const float4*)(wm + 4);
        float  f8 = wm[8];
        float fs[9] = {fA.x, fA.y, fA.z, fA.w, fB.x, fB.y, fB.z, fB.w, f8};
        #pragma unroll
        for (int s = 0; s < 9; s++) {
            ull f2;
            uint32_t fb = __float_as_uint(fs[s]);
            PACK_REPL_F32X2(f2, fb);
            FMA_F32X2(gacc2[s][0], f2, x0, gacc2[s][0]);
            FMA_F32X2(gacc2[s][1], f2, x1, gacc2[s][1]);
            FMA_F32X2(gacc2[s][2], f2, x2, gacc2[s][2]);
            FMA_F32X2(gacc2[s][3], f2, x3, gacc2[s][3]);
        }
    }

    // ---- residual (R13 quarter-ladder) -> res_s, pre-scaled by SQ_RES ----
    {
        const ull* xqp = (const ull*)(in_pc + ((size_t)b_fin * P_ + p) * CI_ + oL * 4);
        ull xq0 = xqp[0], xq1 = xqp[1];
        #pragma unroll
        for (int og = 0; og < 8; og++) {
            float pr[4];
            #pragma unroll
            for (int so = 0; so < 4; so++) {
                int row = og * 4 + (so ^ oL);
                const ull* wr = (const ull*)(wres_s + row * 16 + oL * 4);
                ull t2;
                MUL_F32X2(t2, wr[0], xq0);
                FMA_F32X2(t2, wr[1], xq1, t2);
                uint32_t lo, hi;
                UNPACK_F32X2(lo, hi, t2);
                pr[so] = __uint_as_float(lo) + __uint_as_float(hi);
            }
            pr[0] += __shfl_xor_sync(0xffffffffu, pr[2], 8);
            pr[1] += __shfl_xor_sync(0xffffffffu, pr[3], 8);
            pr[0] += __shfl_xor_sync(0xffffffffu, pr[1], 4);
            res_s[(warp * 8 + b_fin) * 32 + og * 4 + oL] = pr[0] * SQ_RES;
        }
    }
    __syncthreads();   // ww + wres dead -> G_LO region reusable

    // ---- split gacc2 -> bf16 hi/lo rows of G (row = warp*8 + b) ----
    #pragma unroll
    for (int s = 0; s < 9; s++) {
        const int kbase = (2 * s + wp) * 16 + 2 * ih;
        if (!(s == 8 && wp == 1)) {    // dead slot: k>=272 would overrun 560B rows
            #pragma unroll
            for (int sj = 0; sj < 4; sj++) {
                const int row = warp * 8 + bg + 2 * (sj ^ jL);
                uint32_t u0, u1;
                UNPACK_F32X2(u0, u1, gacc2[s][sj]);
                float f0 = __uint_as_float(u0), f1 = __uint_as_float(u1);
                __nv_bfloat16 h0 = __float2bfloat16(f0), h1 = __float2bfloat16(f1);
                __nv_bfloat16 l0 = __float2bfloat16(f0 - __bfloat162float(h0));
                __nv_bfloat16 l1 = __float2bfloat16(f1 - __bfloat162float(h1));
                uint32_t hp = ((uint32_t)__bfloat16_as_ushort(h1) << 16) | __bfloat16_as_ushort(h0);
                uint32_t lp = ((uint32_t)__bfloat16_as_ushort(l1) << 16) | __bfloat16_as_ushort(l0);
                uint32_t off = (uint32_t)row * GSTRIDE + (uint32_t)kbase * 2u;
                *(uint32_t*)(smc + SM_G_HI + off) = hp;
                *(uint32_t*)(smc + SM_G_LO + off) = lp;
            }
        }
    }
    __syncthreads();

    // ---- stage B: warp computes D tile [16 rows x 16 cols] via mma.sync ----
    {
        const int slice = warp >> 1;           // 0..3 (M=64)
        const int nhalf = (warp & 1) * 16;
        const int lm = lane >> 3;
        const int lr = lane & 7;

        const uint32_t a_row = (uint32_t)(slice * 16 + lr + 8 * (lm & 1));
        const uint32_t a_kof = (uint32_t)(8 * (lm >> 1)) * 2u;
        const uint32_t b_row = (uint32_t)(nhalf + 8 * (lm >> 1) + lr);
        const uint32_t b_kof = (uint32_t)(8 * (lm & 1)) * 2u;

        const uint32_t ah_base = smb + SM_G_HI + a_row * GSTRIDE + a_kof;
        const uint32_t al_base = smb + SM_G_LO + a_row * GSTRIDE + a_kof;
        const uint32_t bh_base = smb + SM_W_HI + b_row * GSTRIDE + b_kof;
        const uint32_t bl_base = smb + SM_W_LO + b_row * GSTRIDE + b_kof;

        float c0[4] = {0.f, 0.f, 0.f, 0.f};
        float c1[4] = {0.f, 0.f, 0.f, 0.f};

        #pragma unroll 2
        for (int ks = 0; ks < 17; ks++) {
            const uint32_t ko = (uint32_t)(ks * 32);
            uint32_t ah[4], al[4], bh[4], bl[4];
            LDMATRIX_X4(ah[0], ah[1], ah[2], ah[3], ah_base + ko);
            LDMATRIX_X4(al[0], al[1], al[2], al[3], al_base + ko);
            LDMATRIX_X4(bh[0], bh[1], bh[2], bh[3], bh_base + ko);
            LDMATRIX_X4(bl[0], bl[1], bl[2], bl[3], bl_base + ko);
            MMA_BF16(c0, ah, bh[0], bh[1]);
            MMA_BF16(c1, ah, bh[2], bh[3]);
            MMA_BF16(c0, ah, bl[0], bl[1]);
            MMA_BF16(c1, ah, bl[2], bl[3]);
            MMA_BF16(c0, al, bh[0], bh[1]);
            MMA_BF16(c1, al, bh[2], bh[3]);
        }

        // ---- epilogue ----
        const int lr4 = lane >> 2;
        const int lc2 = (lane & 3) * 2;
        #pragma unroll
        for (int tile = 0; tile < 2; tile++) {
            const float* cc = tile ? c1 : c0;
            const int ncol = nhalf + tile * 8 + lc2;
            #pragma unroll
            for (int half = 0; half < 2; half++) {
                const int row = slice * 16 + lr4 + 8 * half;
                const int pt = row >> 3, b = row & 7;
                const float2 bz = *(const float2*)(bias + ((size_t)(pbase + pt)) * CO_ + ncol);
                const float2 rz = *(const float2*)(res_s + (size_t)row * 32 + ncol);
                float v0 = cc[half * 2 + 0] + bz.x;
                float v1 = cc[half * 2 + 1] + bz.y;
                float e0 = (v0 > 0.0f) ? v0 : expm1f(v0);
                float e1 = (v1 > 0.0f) ? v1 : expm1f(v1);
                float2 o2 = make_float2(e0 * SQ_CONV + rz.x, e1 * SQ_CONV + rz.y);
                *(float2*)(out + ((size_t)b * P_ + (pbase + pt)) * CO_ + ncol) = o2;
            }
        }
    }
}

extern "C" void kernel_launch(void* const* d_in, const int* in_sizes, int n_in,
                              void* d_out, int out_size)
{
    const float* in_pc       = nullptr;
    const float* weights     = nullptr;
    const float* bias        = nullptr;
    const float* w_weights   = nullptr;
    const float* weight_res  = nullptr;
    const int*   neighbor_id = nullptr;

    for (int i = 0; i < n_in; i++) {
        switch (in_sizes[i]) {
            case 2097152: in_pc       = (const float*)d_in[i]; break;
            case 8704:    weights     = (const float*)d_in[i]; break;
            case 524288:  bias        = (const float*)d_in[i]; break;
            case 4456448: w_weights   = (const float*)d_in[i]; break;
            case 512:     weight_res  = (const float*)d_in[i]; break;
            case 262144:  neighbor_id = (const int*)d_in[i];   break;
            default: break;
        }
    }

    cudaFuncSetAttribute(fused_conv_mma_kernel,
                         cudaFuncAttributeMaxDynamicSharedMemorySize, SM_TOTAL);

    fused_conv_mma_kernel<<<P_ / PTS, NTHR, SM_TOTAL>>>(
        in_pc, weights, bias, w_weights, weight_res, neighbor_id, (float*)d_out);
}